// round 7
// baseline (speedup 1.0000x reference)
#include <cuda_runtime.h>

// Quanvolution quantum filter — closed-form Heisenberg-picture evaluation,
// 4 patches (2x2 patch quad) per thread, packed f32x2 across patch pairs.
// K coefficients kept as scalar floats in smem, register-cached, packed on use.

#define BATCH   8192
#define NQUAD   (BATCH * 49)        // 401408 = 3136 * 128

typedef unsigned long long u64;

__device__ __forceinline__ u64 pk2(float lo, float hi) {
    u64 r; asm("mov.b64 %0, {%1, %2};" : "=l"(r) : "f"(lo), "f"(hi)); return r;
}
__device__ __forceinline__ u64 bc2(float v) { return pk2(v, v); }
__device__ __forceinline__ u64 mul2(u64 a, u64 b) {
    u64 r; asm("mul.rn.f32x2 %0, %1, %2;" : "=l"(r) : "l"(a), "l"(b)); return r;
}
__device__ __forceinline__ u64 fma2(u64 a, u64 b, u64 c) {
    u64 r; asm("fma.rn.f32x2 %0, %1, %2, %3;" : "=l"(r) : "l"(a), "l"(b), "l"(c)); return r;
}
__device__ __forceinline__ void upk2(u64 v, float& lo, float& hi) {
    asm("mov.b64 {%0, %1}, %2;" : "=f"(lo), "=f"(hi) : "l"(v));
}

// Closed-form expectations for one packed patch pair.
// Z_v = cos(a_v), X_v = sin(a_v), a_v = x_v + params[0][v].
__device__ __forceinline__ void eval_pair(
    const float* __restrict__ k,
    u64 Z0, u64 Z1, u64 Z2, u64 Z3,
    u64 X0, u64 X1, u64 X2, u64 X3,
    u64& e0, u64& e1, u64& e2, u64& e3)
{
    u64 zz01 = mul2(Z0, Z1), zz02 = mul2(Z0, Z2), zz03 = mul2(Z0, Z3);
    u64 zz13 = mul2(Z1, Z3), zz23 = mul2(Z2, Z3);
    u64 xx01 = mul2(X0, X1), xx02 = mul2(X0, X2), xx03 = mul2(X0, X3);
    u64 xx12 = mul2(X1, X2), xx13 = mul2(X1, X3), xx23 = mul2(X2, X3);
    u64 zx23 = mul2(Z2, X3);

    // E[Z_0] = k0*z0z1z3 + k1*x0x1z2x3 + k2*x1x2z3 + k3*x0
    e0 = mul2(bc2(k[0]), mul2(zz01, Z3));
    e0 = fma2(bc2(k[1]), mul2(xx01, zx23), e0);
    e0 = fma2(bc2(k[2]), mul2(xx12, Z3), e0);
    e0 = fma2(bc2(k[3]), X0, e0);

    // E[Z_1] = k4*z0z2z3 + k5*x0x2
    e1 = mul2(bc2(k[4]), mul2(Z0, zz23));
    e1 = fma2(bc2(k[5]), xx02, e1);

    // E[Z_2] = k6*z1z3 + k7*z0x1x2z3 + k8*x0x1z2 + k9*x0x3
    e2 = mul2(bc2(k[6]), zz13);
    e2 = fma2(bc2(k[7]), mul2(xx12, zz03), e2);
    e2 = fma2(bc2(k[8]), mul2(xx01, Z2), e2);
    e2 = fma2(bc2(k[9]), xx03, e2);

    // E[Z_3] = k10*z0z2 + k11*z1x2x3 + k12*x0x2z3 + k13*z2x3
    //        + k14*z0x1x3 + k15*z0z1x2 + k16*x0z1z2z3 + k17*x1
    e3 = mul2(bc2(k[10]), zz02);
    e3 = fma2(bc2(k[11]), mul2(Z1, xx23), e3);
    e3 = fma2(bc2(k[12]), mul2(xx02, Z3), e3);
    e3 = fma2(bc2(k[13]), zx23, e3);
    e3 = fma2(bc2(k[14]), mul2(Z0, xx13), e3);
    e3 = fma2(bc2(k[15]), mul2(zz01, X2), e3);
    e3 = fma2(bc2(k[16]), mul2(mul2(zz13, Z2), X0), e3);
    e3 = fma2(bc2(k[17]), X1, e3);
}

__global__ __launch_bounds__(128)
void quanv7_kernel(const float* __restrict__ x,
                   const float* __restrict__ params,
                   float* __restrict__ out)
{
    // Ks[0..17]: coefficient products; Ks[18..21]: params[0][v] (angle shift).
    __shared__ __align__(16) float Ks[24];
    if (threadIdx.x == 0) {
        float c[4], s[4];
        #pragma unroll
        for (int v = 0; v < 4; ++v) {
            Ks[18 + v] = params[v];
            __sincosf(params[4 + v], &s[v], &c[v]);
        }
        Ks[0]  =  c[1] * c[2] * c[3];
        Ks[1]  = -c[1] * c[2] * s[3];
        Ks[2]  = -s[1] * c[2] * c[3];
        Ks[3]  = -s[1] * s[2] * s[3];
        Ks[4]  =  c[0] * c[1];
        Ks[5]  =  s[0] * s[1];
        Ks[6]  =  c[0] * c[1] * c[2];
        Ks[7]  = -c[0] * s[1] * c[2];
        Ks[8]  = -s[0] * c[1] * c[2];
        Ks[9]  = -s[0] * s[1] * s[2];
        Ks[10] =  c[0] * c[1] * c[2] * c[3];
        Ks[11] = -c[0] * c[1] * s[2] * c[3];
        Ks[12] =  s[0] * s[1] * c[2] * c[3];
        Ks[13] =  s[0] * c[1] * c[2] * s[3];
        Ks[14] =  c[0] * s[1] * s[2] * c[3];
        Ks[15] = -s[0] * c[1] * s[2] * s[3];
        Ks[16] = -c[0] * s[1] * s[2] * s[3];
        Ks[17] =  s[0] * s[1] * s[2] * s[3];
        Ks[22] = 0.f; Ks[23] = 0.f;
    }
    __syncthreads();

    // Register-cache coefficients + shifts via 6 LDS.128.
    float k[18], P0, P1, P2, P3;
    {
        const float4* Kv = reinterpret_cast<const float4*>(Ks);
        float4 a = Kv[0], b4 = Kv[1], c4 = Kv[2], d4 = Kv[3], e4 = Kv[4], f4 = Kv[5];
        k[0]=a.x; k[1]=a.y; k[2]=a.z; k[3]=a.w;
        k[4]=b4.x; k[5]=b4.y; k[6]=b4.z; k[7]=b4.w;
        k[8]=c4.x; k[9]=c4.y; k[10]=c4.z; k[11]=c4.w;
        k[12]=d4.x; k[13]=d4.y; k[14]=d4.z; k[15]=d4.w;
        k[16]=e4.x; k[17]=e4.y; P0=e4.z; P1=e4.w;
        P2=f4.x; P3=f4.y;
    }

    int q = blockIdx.x * blockDim.x + threadIdx.x;   // quad index (exact grid)

    int b  = q / 49;                 // image
    int rem = q - b * 49;
    int rp = rem / 7;                // patch-row pair 0..6  (patch rows 2rp, 2rp+1)
    int cp = rem - rp * 7;           // patch-col pair 0..6  (patch cols 2cp, 2cp+1)

    const float* img = x + b * 784 + (4 * rp) * 28 + 4 * cp;
    float4 row0 = *reinterpret_cast<const float4*>(img);
    float4 row1 = *reinterpret_cast<const float4*>(img + 28);
    float4 row2 = *reinterpret_cast<const float4*>(img + 56);
    float4 row3 = *reinterpret_cast<const float4*>(img + 84);

    // ---- pair A: patches (2rp, 2cp) [lo lane], (2rp, 2cp+1) [hi lane] ----
    float zL0,xL0,zL1,xL1,zL2,xL2,zL3,xL3, zH0,xH0,zH1,xH1,zH2,xH2,zH3,xH3;
    __sincosf(row0.x + P0, &xL0, &zL0);
    __sincosf(row0.y + P1, &xL1, &zL1);
    __sincosf(row1.x + P2, &xL2, &zL2);
    __sincosf(row1.y + P3, &xL3, &zL3);
    __sincosf(row0.z + P0, &xH0, &zH0);
    __sincosf(row0.w + P1, &xH1, &zH1);
    __sincosf(row1.z + P2, &xH2, &zH2);
    __sincosf(row1.w + P3, &xH3, &zH3);

    u64 a0, a1, a2, a3;
    eval_pair(k,
              pk2(zL0,zH0), pk2(zL1,zH1), pk2(zL2,zH2), pk2(zL3,zH3),
              pk2(xL0,xH0), pk2(xL1,xH1), pk2(xL2,xH2), pk2(xL3,xH3),
              a0, a1, a2, a3);

    // ---- pair B: patches (2rp+1, 2cp) [lo], (2rp+1, 2cp+1) [hi] ----
    __sincosf(row2.x + P0, &xL0, &zL0);
    __sincosf(row2.y + P1, &xL1, &zL1);
    __sincosf(row3.x + P2, &xL2, &zL2);
    __sincosf(row3.y + P3, &xL3, &zL3);
    __sincosf(row2.z + P0, &xH0, &zH0);
    __sincosf(row2.w + P1, &xH1, &zH1);
    __sincosf(row3.z + P2, &xH2, &zH2);
    __sincosf(row3.w + P3, &xH3, &zH3);

    u64 b0, b1, b2, b3;
    eval_pair(k,
              pk2(zL0,zH0), pk2(zL1,zH1), pk2(zL2,zH2), pk2(zL3,zH3),
              pk2(xL0,xH0), pk2(xL1,xH1), pk2(xL2,xH2), pk2(xL3,xH3),
              b0, b1, b2, b3);

    // ---- stores: 4 float4 (one per patch) ----
    float4 oA0, oA1, oB0, oB1;
    upk2(a0, oA0.x, oA1.x); upk2(a1, oA0.y, oA1.y);
    upk2(a2, oA0.z, oA1.z); upk2(a3, oA0.w, oA1.w);
    upk2(b0, oB0.x, oB1.x); upk2(b1, oB0.y, oB1.y);
    upk2(b2, oB0.z, oB1.z); upk2(b3, oB0.w, oB1.w);

    int n00 = b * 196 + (2 * rp) * 14 + 2 * cp;   // patch (2rp, 2cp)
    float4* out4 = reinterpret_cast<float4*>(out);
    out4[n00]      = oA0;
    out4[n00 + 1]  = oA1;
    out4[n00 + 14] = oB0;
    out4[n00 + 15] = oB1;
}

extern "C" void kernel_launch(void* const* d_in, const int* in_sizes, int n_in,
                              void* d_out, int out_size)
{
    const float* x      = (const float*)d_in[0];   // (8192,1,28,28) float32
    const float* params = (const float*)d_in[1];   // (2,4) float32
    float* out          = (float*)d_out;           // (8192, 784) float32

    (void)in_sizes; (void)n_in; (void)out_size;

    const int threads = 128;
    const int blocks  = NQUAD / threads;           // 3136, exact
    quanv7_kernel<<<blocks, threads>>>(x, params, out);
}

// round 8
// speedup vs baseline: 1.0201x; 1.0201x over previous
#include <cuda_runtime.h>

// Quanvolution quantum filter — closed-form Heisenberg-picture evaluation.
// 2 patches per thread (packed f32x2), K coefficients pre-broadcast as u64
// in smem and fetched as 9x LDS.128 pairs; input LDGs hoisted above the
// block barrier to overlap global latency with thread-0's init.

#define BATCH   8192
#define NPATCH  196
#define NTOT    (BATCH * NPATCH)
#define NPAIR   (NTOT / 2)          // 802816 = 6272 * 128

typedef unsigned long long u64;

__device__ __forceinline__ u64 pk2(float lo, float hi) {
    u64 r; asm("mov.b64 %0, {%1, %2};" : "=l"(r) : "f"(lo), "f"(hi)); return r;
}
__device__ __forceinline__ u64 mul2(u64 a, u64 b) {
    u64 r; asm("mul.rn.f32x2 %0, %1, %2;" : "=l"(r) : "l"(a), "l"(b)); return r;
}
__device__ __forceinline__ u64 fma2(u64 a, u64 b, u64 c) {
    u64 r; asm("fma.rn.f32x2 %0, %1, %2, %3;" : "=l"(r) : "l"(a), "l"(b), "l"(c)); return r;
}
__device__ __forceinline__ void upk2(u64 v, float& lo, float& hi) {
    asm("mov.b64 {%0, %1}, %2;" : "=f"(lo), "=f"(hi) : "l"(v));
}

__global__ __launch_bounds__(128, 12)
void quanv8_kernel(const float* __restrict__ x,
                   const float* __restrict__ params,
                   float* __restrict__ out)
{
    __shared__ __align__(16) u64 Ku[18];   // coefficient, broadcast in both lanes
    __shared__ __align__(16) float Pf[4];  // params[0][v] angle shifts

    // ---- index math + input loads FIRST (overlap with init below) ----
    int q = blockIdx.x * blockDim.x + threadIdx.x;   // pair index (exact grid)
    int b  = q / 98;
    int pp = q - b * 98;
    int r  = pp / 7;
    int j  = pp - r * 7;

    const float* img = x + b * 784;
    float4 top = *reinterpret_cast<const float4*>(img + (2 * r) * 28 + 4 * j);
    float4 bot = *reinterpret_cast<const float4*>(img + (2 * r + 1) * 28 + 4 * j);

    if (threadIdx.x == 0) {
        float c[4], s[4];
        #pragma unroll
        for (int v = 0; v < 4; ++v) {
            Pf[v] = params[v];
            __sincosf(params[4 + v], &s[v], &c[v]);
        }
        float k[18];
        k[0]  =  c[1] * c[2] * c[3];          // E0: z0z1z3
        k[1]  = -c[1] * c[2] * s[3];          // E0: x0x1z2x3
        k[2]  = -s[1] * c[2] * c[3];          // E0: x1x2z3
        k[3]  = -s[1] * s[2] * s[3];          // E0: x0
        k[4]  =  c[0] * c[1];                 // E1: z0z2z3
        k[5]  =  s[0] * s[1];                 // E1: x0x2
        k[6]  =  c[0] * c[1] * c[2];          // E2: z1z3
        k[7]  = -c[0] * s[1] * c[2];          // E2: z0x1x2z3
        k[8]  = -s[0] * c[1] * c[2];          // E2: x0x1z2
        k[9]  = -s[0] * s[1] * s[2];          // E2: x0x3
        k[10] =  c[0] * c[1] * c[2] * c[3];   // E3: z0z2
        k[11] = -c[0] * c[1] * s[2] * c[3];   // E3: z1x2x3
        k[12] =  s[0] * s[1] * c[2] * c[3];   // E3: x0x2z3
        k[13] =  s[0] * c[1] * c[2] * s[3];   // E3: z2x3
        k[14] =  c[0] * s[1] * s[2] * c[3];   // E3: z0x1x3
        k[15] = -s[0] * c[1] * s[2] * s[3];   // E3: z0z1x2
        k[16] = -c[0] * s[1] * s[2] * s[3];   // E3: x0z1z2z3
        k[17] =  s[0] * s[1] * s[2] * s[3];   // E3: x1
        #pragma unroll
        for (int i = 0; i < 18; ++i) Ku[i] = pk2(k[i], k[i]);
    }
    __syncthreads();

    float4 P = *reinterpret_cast<const float4*>(Pf);

    // Full angles a_v = x_v + params[0][v]; Z = cos a, X = sin a.
    float zA0, xA0, zA1, xA1, zA2, xA2, zA3, xA3;   // patch A (lo lane)
    float zB0, xB0, zB1, xB1, zB2, xB2, zB3, xB3;   // patch B (hi lane)
    __sincosf(top.x + P.x, &xA0, &zA0);
    __sincosf(top.y + P.y, &xA1, &zA1);
    __sincosf(bot.x + P.z, &xA2, &zA2);
    __sincosf(bot.y + P.w, &xA3, &zA3);
    __sincosf(top.z + P.x, &xB0, &zB0);
    __sincosf(top.w + P.y, &xB1, &zB1);
    __sincosf(bot.z + P.z, &xB2, &zB2);
    __sincosf(bot.w + P.w, &xB3, &zB3);

    u64 Z0 = pk2(zA0, zB0), X0 = pk2(xA0, xB0);
    u64 Z1 = pk2(zA1, zB1), X1 = pk2(xA1, xB1);
    u64 Z2 = pk2(zA2, zB2), X2 = pk2(xA2, xB2);
    u64 Z3 = pk2(zA3, zB3), X3 = pk2(xA3, xB3);

    // Shared pair products.
    u64 zz01 = mul2(Z0, Z1), zz02 = mul2(Z0, Z2), zz03 = mul2(Z0, Z3);
    u64 zz13 = mul2(Z1, Z3), zz23 = mul2(Z2, Z3);
    u64 xx01 = mul2(X0, X1), xx02 = mul2(X0, X2), xx03 = mul2(X0, X3);
    u64 xx12 = mul2(X1, X2), xx13 = mul2(X1, X3), xx23 = mul2(X2, X3);
    u64 zx23 = mul2(Z2, X3);

    const ulonglong2* K2 = reinterpret_cast<const ulonglong2*>(Ku);

    // E[Z_0] = k0*z0z1z3 + k1*x0x1z2x3 + k2*x1x2z3 + k3*x0
    ulonglong2 kA = K2[0];                 // k0,k1
    ulonglong2 kB = K2[1];                 // k2,k3
    u64 e0 = mul2(kA.x, mul2(zz01, Z3));
    e0 = fma2(kA.y, mul2(xx01, zx23), e0);
    e0 = fma2(kB.x, mul2(xx12, Z3), e0);
    e0 = fma2(kB.y, X0, e0);

    // E[Z_1] = k4*z0z2z3 + k5*x0x2
    ulonglong2 kC = K2[2];                 // k4,k5
    u64 e1 = mul2(kC.x, mul2(Z0, zz23));
    e1 = fma2(kC.y, xx02, e1);

    // E[Z_2] = k6*z1z3 + k7*z0x1x2z3 + k8*x0x1z2 + k9*x0x3
    ulonglong2 kD = K2[3];                 // k6,k7
    ulonglong2 kE = K2[4];                 // k8,k9
    u64 e2 = mul2(kD.x, zz13);
    e2 = fma2(kD.y, mul2(xx12, zz03), e2);
    e2 = fma2(kE.x, mul2(xx01, Z2), e2);
    e2 = fma2(kE.y, xx03, e2);

    // E[Z_3] = k10*z0z2 + k11*z1x2x3 + k12*x0x2z3 + k13*z2x3
    //        + k14*z0x1x3 + k15*z0z1x2 + k16*x0z1z2z3 + k17*x1
    ulonglong2 kF = K2[5];                 // k10,k11
    ulonglong2 kG = K2[6];                 // k12,k13
    ulonglong2 kH = K2[7];                 // k14,k15
    ulonglong2 kI = K2[8];                 // k16,k17
    u64 e3 = mul2(kF.x, zz02);
    e3 = fma2(kF.y, mul2(Z1, xx23), e3);
    e3 = fma2(kG.x, mul2(xx02, Z3), e3);
    e3 = fma2(kG.y, zx23, e3);
    e3 = fma2(kH.x, mul2(Z0, xx13), e3);
    e3 = fma2(kH.y, mul2(zz01, X2), e3);
    e3 = fma2(kI.x, mul2(mul2(zz13, Z2), X0), e3);
    e3 = fma2(kI.y, X1, e3);

    float4 o0, o1;
    upk2(e0, o0.x, o1.x);
    upk2(e1, o0.y, o1.y);
    upk2(e2, o0.z, o1.z);
    upk2(e3, o0.w, o1.w);

    int n0 = 2 * q;
    reinterpret_cast<float4*>(out)[n0]     = o0;
    reinterpret_cast<float4*>(out)[n0 + 1] = o1;
}

extern "C" void kernel_launch(void* const* d_in, const int* in_sizes, int n_in,
                              void* d_out, int out_size)
{
    const float* x      = (const float*)d_in[0];   // (8192,1,28,28) float32
    const float* params = (const float*)d_in[1];   // (2,4) float32
    float* out          = (float*)d_out;           // (8192, 784) float32

    (void)in_sizes; (void)n_in; (void)out_size;

    const int threads = 128;
    const int blocks  = NPAIR / threads;           // 6272, exact
    quanv8_kernel<<<blocks, threads>>>(x, params, out);
}